// round 7
// baseline (speedup 1.0000x reference)
#include <cuda_runtime.h>
#include <cstdint>

#define DEG2RAD  0.017453292519943295f
#define PI_F     3.14159265358979323846f
#define PIO2_F   1.57079632679489661923f
#define EARTH_R  6371.009f

#define NBLOCKS  888     // 148 SMs * 6 CTAs (smem-limited occupancy)
#define NTHREADS 256
#define TILE_F4  256     // float4 per stream per tile (4 KB)
#define STAGES   3
#define STAGE_BYTES (3u * TILE_F4 * 16u)   // 12288

__device__ float g_partials[NBLOCKS];
__device__ unsigned int g_count = 0;

// ---------- PTX helpers ----------
__device__ __forceinline__ void mbar_init(uint32_t bar, uint32_t cnt) {
    asm volatile("mbarrier.init.shared.b64 [%0], %1;" :: "r"(bar), "r"(cnt) : "memory");
}
__device__ __forceinline__ void mbar_expect_tx(uint32_t bar, uint32_t tx) {
    asm volatile("mbarrier.arrive.expect_tx.shared.b64 _, [%0], %1;" :: "r"(bar), "r"(tx) : "memory");
}
__device__ __forceinline__ void bulk_g2s(uint32_t dst, const void* src, uint32_t bytes, uint32_t bar) {
    asm volatile("cp.async.bulk.shared::cluster.global.mbarrier::complete_tx::bytes [%0], [%1], %2, [%3];"
                 :: "r"(dst), "l"(src), "r"(bytes), "r"(bar) : "memory");
}
__device__ __forceinline__ void mbar_wait_parity(uint32_t bar, uint32_t parity) {
    uint32_t done;
    asm volatile("{\n\t.reg .pred p;\n\t"
                 "mbarrier.try_wait.parity.acquire.cta.shared::cta.b64 p, [%1], %2;\n\t"
                 "selp.b32 %0, 1, 0, p;\n\t}"
                 : "=r"(done) : "r"(bar), "r"(parity) : "memory");
    if (!done) {
        asm volatile("{\n\t.reg .pred P1;\n\t"
                     "WL_%=:\n\t"
                     "mbarrier.try_wait.parity.acquire.cta.shared::cta.b64 P1, [%0], %1, 0x989680;\n\t"
                     "@P1 bra.uni WD_%=;\n\t"
                     "bra.uni WL_%=;\n\t"
                     "WD_%=:\n\t}"
                     :: "r"(bar), "r"(parity) : "memory");
    }
}
__device__ __forceinline__ float sqrt_approx(float x) {
    float r; asm("sqrt.approx.f32 %0, %1;" : "=f"(r) : "f"(x)); return r;
}

// ---------- math (identical to R5/R6) ----------
__device__ __forceinline__ float fast_atan2_pos(float num, float den)
{
    float ax = fabsf(den);
    float mn = fminf(num, ax);
    float mx = fmaxf(fmaxf(num, ax), 1e-30f);
    float z  = __fdividef(mn, mx);
    float z2 = z * z;
    float p = -0.0117212f;
    p = fmaf(p, z2,  0.05265332f);
    p = fmaf(p, z2, -0.11643287f);
    p = fmaf(p, z2,  0.19354346f);
    p = fmaf(p, z2, -0.33262347f);
    p = fmaf(p, z2,  0.99997726f);
    float a = z * p;
    if (num > ax)  a = PIO2_F - a;
    if (den < 0.f) a = PI_F - a;
    return a;
}

__device__ __forceinline__ void sincos_small(float x, float* s, float* c)
{
    float x2 = x * x;
    float ps = fmaf(x2, -1.9841270e-4f, 8.3333333e-3f);
    ps = fmaf(x2, ps, -0.16666667f);
    ps = fmaf(x2, ps, 1.0f);
    *s = x * ps;
    float pc = fmaf(x2, 2.4801587e-5f, -1.3888889e-3f);
    pc = fmaf(x2, pc, 4.1666667e-2f);
    pc = fmaf(x2, pc, -0.5f);
    pc = fmaf(x2, pc, 1.0f);
    *c = pc;
}

__device__ __forceinline__ float gd_angle(float p_lat, float p_lng,
                                          float t_lat, float t_lng,
                                          float s_lat,
                                          float mr, float kr, float kd,
                                          float m0r, float sd0r)
{
    float site_r = fmaf(s_lat, sd0r, m0r);
    float lat1 = fmaf(p_lat, kr, mr) + site_r;
    float lat2 = fmaf(t_lat, kr, mr) + site_r;
    lat1 = fminf(fmaxf(lat1, -PIO2_F), PIO2_F);  // clamp predicted lat only
    float delta = (t_lng - p_lng) * kd;

    float s1, c1, s2, c2, sd, cd;
    __sincosf(lat1, &s1, &c1);
    __sincosf(lat2, &s2, &c2);
    sincos_small(delta, &sd, &cd);

    float a = c2 * sd;
    float b = fmaf(c1, s2, -(s1 * c2) * cd);
    float num = sqrt_approx(fmaf(a, a, b * b));
    float den = fmaf(s1, s2, (c1 * c2) * cd);
    return fast_atan2_pos(num, den);
}

// ---------- kernel ----------
__global__ void __launch_bounds__(NTHREADS)
gd_tma(const float4* __restrict__ pred,
       const float4* __restrict__ tru,
       const float4* __restrict__ site,
       const float* __restrict__ mean_speed,
       const float* __restrict__ std_speed,
       const float* __restrict__ mean,
       const float* __restrict__ stdv,
       int n_tiles, int rem_base, int rem, float scale, float* __restrict__ out)
{
    // [stage][stream][elt]: stream 0=pred 1=true 2=site
    __shared__ float4 buf[STAGES][3][TILE_F4];
    __shared__ alignas(8) unsigned long long mbar[STAGES];

    const float mr   = __ldg(&mean_speed[0]) * DEG2RAD;
    const float kr   = __ldg(&std_speed[0]) * DEG2RAD;
    const float kd   = __ldg(&std_speed[1]) * DEG2RAD;
    const float m0r  = __ldg(&mean[0]) * DEG2RAD;
    const float sd0r = __ldg(&stdv[0]) * DEG2RAD;

    const int tid  = threadIdx.x;
    const int grid = gridDim.x;

    uint32_t bar0 = (uint32_t)__cvta_generic_to_shared(&mbar[0]);

    if (tid == 0) {
        #pragma unroll
        for (int s = 0; s < STAGES; s++) mbar_init(bar0 + 8u * s, 1u);
    }
    __syncthreads();

    // tiles owned by this CTA: g = bid, bid+grid, ...
    const int g0 = blockIdx.x;
    int mine = (g0 < n_tiles) ? ((n_tiles - 1 - g0) / grid + 1) : 0;

    // prologue: fill the ring
    if (tid == 0) {
        int npre = mine < STAGES ? mine : STAGES;
        for (int k = 0; k < npre; k++) {
            long long base = (long long)(g0 + (long long)k * grid) * TILE_F4;
            uint32_t bar = bar0 + 8u * k;
            uint32_t d = (uint32_t)__cvta_generic_to_shared(&buf[k][0][0]);
            mbar_expect_tx(bar, STAGE_BYTES);
            bulk_g2s(d,                        pred + base, TILE_F4 * 16u, bar);
            bulk_g2s(d + TILE_F4 * 16u,        tru  + base, TILE_F4 * 16u, bar);
            bulk_g2s(d + 2u * TILE_F4 * 16u,   site + base, TILE_F4 * 16u, bar);
        }
    }

    float acc = 0.0f;
    for (int k = 0; k < mine; k++) {
        int s  = k % STAGES;
        uint32_t ph = (uint32_t)((k / STAGES) & 1);
        mbar_wait_parity(bar0 + 8u * s, ph);

        float4 p  = buf[s][0][tid];
        float4 t  = buf[s][1][tid];
        float4 sv = buf[s][2][tid];
        acc += gd_angle(p.x, p.y, t.x, t.y, sv.x, mr, kr, kd, m0r, sd0r);
        acc += gd_angle(p.z, p.w, t.z, t.w, sv.z, mr, kr, kd, m0r, sd0r);

        __syncthreads();   // everyone done reading stage s -> safe to refill

        if (tid == 0 && (k + STAGES) < mine) {
            long long base = (long long)(g0 + (long long)(k + STAGES) * grid) * TILE_F4;
            uint32_t bar = bar0 + 8u * s;
            uint32_t d = (uint32_t)__cvta_generic_to_shared(&buf[s][0][0]);
            mbar_expect_tx(bar, STAGE_BYTES);
            bulk_g2s(d,                        pred + base, TILE_F4 * 16u, bar);
            bulk_g2s(d + TILE_F4 * 16u,        tru  + base, TILE_F4 * 16u, bar);
            bulk_g2s(d + 2u * TILE_F4 * 16u,   site + base, TILE_F4 * 16u, bar);
        }
    }

    // remainder float4s (none for B=8.4M, kept for generality): CTA 0 direct loads
    if (blockIdx.x == 0 && tid < rem) {
        float4 p  = __ldg(&pred[rem_base + tid]);
        float4 t  = __ldg(&tru [rem_base + tid]);
        float4 sv = __ldg(&site[rem_base + tid]);
        acc += gd_angle(p.x, p.y, t.x, t.y, sv.x, mr, kr, kd, m0r, sd0r);
        acc += gd_angle(p.z, p.w, t.z, t.w, sv.z, mr, kr, kd, m0r, sd0r);
    }

    // intra-block reduce
    #pragma unroll
    for (int o = 16; o > 0; o >>= 1)
        acc += __shfl_xor_sync(0xffffffffu, acc, o);

    __shared__ float sm[NTHREADS / 32];
    __shared__ bool is_last;
    int lane = tid & 31;
    int warp = tid >> 5;
    if (lane == 0) sm[warp] = acc;
    __syncthreads();

    if (tid == 0) {
        float v = 0.0f;
        #pragma unroll
        for (int w = 0; w < NTHREADS / 32; w++) v += sm[w];
        g_partials[blockIdx.x] = v;
        __threadfence();
        unsigned int ticket = atomicAdd(&g_count, 1u);
        is_last = (ticket == gridDim.x - 1);
        if (is_last) g_count = 0;   // reset for next graph replay
    }
    __syncthreads();

    if (is_last) {
        float v = 0.0f;
        for (int j = tid; j < NBLOCKS; j += NTHREADS)
            v += g_partials[j];
        #pragma unroll
        for (int o = 16; o > 0; o >>= 1)
            v += __shfl_xor_sync(0xffffffffu, v, o);
        if (lane == 0) sm[warp] = v;
        __syncthreads();
        if (tid == 0) {
            float t = 0.0f;
            #pragma unroll
            for (int w = 0; w < NTHREADS / 32; w++) t += sm[w];
            out[0] = t * scale;
        }
    }
}

extern "C" void kernel_launch(void* const* d_in, const int* in_sizes, int n_in,
                              void* d_out, int out_size)
{
    const float4* pred = (const float4*)d_in[0];
    const float4* tru  = (const float4*)d_in[1];
    const float*  ms   = (const float*)d_in[2];
    const float*  ss   = (const float*)d_in[3];
    const float4* site = (const float4*)d_in[4];
    const float*  mn   = (const float*)d_in[5];
    const float*  sd   = (const float*)d_in[6];

    int n4 = in_sizes[0] / 4;                 // float4 count (2 rows each)
    int n_tiles = n4 / TILE_F4;
    int rem_base = n_tiles * TILE_F4;
    int rem = n4 - rem_base;                  // 0 for this shape
    long long B = (long long)in_sizes[0] / 2; // row count
    float scale = (float)((double)EARTH_R / (double)B);

    gd_tma<<<NBLOCKS, NTHREADS>>>(pred, tru, site, ms, ss, mn, sd,
                                  n_tiles, rem_base, rem, scale, (float*)d_out);
}

// round 8
// speedup vs baseline: 1.0193x; 1.0193x over previous
#include <cuda_runtime.h>
#include <cstdint>

#define DEG2RAD  0.017453292519943295f
#define PI_F     3.14159265358979323846f
#define PIO2_F   1.57079632679489661923f
#define EARTH_R  6371.009f

#define NBLOCKS  1184    // 148 SMs * 8 CTAs
#define NTHREADS 256
#define TILE_F4  256     // one float4 per thread per stream per tile

__device__ float g_partials[NBLOCKS];
__device__ unsigned int g_count = 0;

// ---------- cp.async helpers ----------
__device__ __forceinline__ void cp16(uint32_t dst, const void* src) {
    asm volatile("cp.async.cg.shared.global [%0], [%1], 16;"
                 :: "r"(dst), "l"(src) : "memory");
}
__device__ __forceinline__ void cp_commit() {
    asm volatile("cp.async.commit_group;" ::: "memory");
}
__device__ __forceinline__ void cp_wait1() {
    asm volatile("cp.async.wait_group 1;" ::: "memory");
}
__device__ __forceinline__ void cp_wait0() {
    asm volatile("cp.async.wait_group 0;" ::: "memory");
}
__device__ __forceinline__ float sqrt_approx(float x) {
    float r; asm("sqrt.approx.f32 %0, %1;" : "=f"(r) : "f"(x)); return r;
}

// ---------- math (identical to R5/R6) ----------
__device__ __forceinline__ float fast_atan2_pos(float num, float den)
{
    float ax = fabsf(den);
    float mn = fminf(num, ax);
    float mx = fmaxf(fmaxf(num, ax), 1e-30f);
    float z  = __fdividef(mn, mx);
    float z2 = z * z;
    float p = -0.0117212f;
    p = fmaf(p, z2,  0.05265332f);
    p = fmaf(p, z2, -0.11643287f);
    p = fmaf(p, z2,  0.19354346f);
    p = fmaf(p, z2, -0.33262347f);
    p = fmaf(p, z2,  0.99997726f);
    float a = z * p;
    if (num > ax)  a = PIO2_F - a;
    if (den < 0.f) a = PI_F - a;
    return a;
}

__device__ __forceinline__ void sincos_small(float x, float* s, float* c)
{
    float x2 = x * x;
    float ps = fmaf(x2, -1.9841270e-4f, 8.3333333e-3f);
    ps = fmaf(x2, ps, -0.16666667f);
    ps = fmaf(x2, ps, 1.0f);
    *s = x * ps;
    float pc = fmaf(x2, 2.4801587e-5f, -1.3888889e-3f);
    pc = fmaf(x2, pc, 4.1666667e-2f);
    pc = fmaf(x2, pc, -0.5f);
    pc = fmaf(x2, pc, 1.0f);
    *c = pc;
}

__device__ __forceinline__ float gd_angle(float p_lat, float p_lng,
                                          float t_lat, float t_lng,
                                          float s_lat,
                                          float mr, float kr, float kd,
                                          float m0r, float sd0r)
{
    float site_r = fmaf(s_lat, sd0r, m0r);
    float lat1 = fmaf(p_lat, kr, mr) + site_r;
    float lat2 = fmaf(t_lat, kr, mr) + site_r;
    lat1 = fminf(fmaxf(lat1, -PIO2_F), PIO2_F);  // clamp predicted lat only
    float delta = (t_lng - p_lng) * kd;

    float s1, c1, s2, c2, sd, cd;
    __sincosf(lat1, &s1, &c1);
    __sincosf(lat2, &s2, &c2);
    sincos_small(delta, &sd, &cd);

    float a = c2 * sd;
    float b = fmaf(c1, s2, -(s1 * c2) * cd);
    float num = sqrt_approx(fmaf(a, a, b * b));
    float den = fmaf(s1, s2, (c1 * c2) * cd);
    return fast_atan2_pos(num, den);
}

// ---------- kernel ----------
__global__ void __launch_bounds__(NTHREADS)
gd_cpasync(const float4* __restrict__ pred,
           const float4* __restrict__ tru,
           const float4* __restrict__ site,
           const float* __restrict__ mean_speed,
           const float* __restrict__ std_speed,
           const float* __restrict__ mean,
           const float* __restrict__ stdv,
           int n_tiles, int rem_base, int rem, float scale,
           float* __restrict__ out)
{
    // [stage][stream][thread] — each thread touches ONLY its own slots:
    // no __syncthreads, no mbarrier; per-thread commit-group pipeline.
    __shared__ float4 buf[2][3][NTHREADS];

    const float mr   = __ldg(&mean_speed[0]) * DEG2RAD;
    const float kr   = __ldg(&std_speed[0]) * DEG2RAD;
    const float kd   = __ldg(&std_speed[1]) * DEG2RAD;
    const float m0r  = __ldg(&mean[0]) * DEG2RAD;
    const float sd0r = __ldg(&stdv[0]) * DEG2RAD;

    const int tid  = threadIdx.x;
    const int grid = gridDim.x;
    const int g0   = blockIdx.x;
    const int mine = (g0 < n_tiles) ? ((n_tiles - 1 - g0) / grid + 1) : 0;

    const uint32_t s_p0 = (uint32_t)__cvta_generic_to_shared(&buf[0][0][tid]);
    const uint32_t s_t0 = (uint32_t)__cvta_generic_to_shared(&buf[0][1][tid]);
    const uint32_t s_s0 = (uint32_t)__cvta_generic_to_shared(&buf[0][2][tid]);
    const uint32_t stage_sz = 3u * NTHREADS * 16u;   // bytes between stage 0 and 1

    float acc = 0.0f;

    if (mine > 0) {
        // prologue: stage 0 = tile 0
        {
            long long e = (long long)g0 * TILE_F4 + tid;
            cp16(s_p0, pred + e);
            cp16(s_t0, tru  + e);
            cp16(s_s0, site + e);
            cp_commit();
        }
        for (int k = 0; k < mine; k++) {
            int cur = k & 1;
            if (k + 1 < mine) {
                // issue next tile into the other stage, then wait for current
                long long e = ((long long)g0 + (long long)(k + 1) * grid) * TILE_F4 + tid;
                uint32_t off = (cur ^ 1) * stage_sz;
                cp16(s_p0 + off, pred + e);
                cp16(s_t0 + off, tru  + e);
                cp16(s_s0 + off, site + e);
                cp_commit();
                cp_wait1();   // oldest group (tile k) complete
            } else {
                cp_wait0();
            }

            float4 p  = buf[cur][0][tid];
            float4 t  = buf[cur][1][tid];
            float4 sv = buf[cur][2][tid];
            acc += gd_angle(p.x, p.y, t.x, t.y, sv.x, mr, kr, kd, m0r, sd0r);
            acc += gd_angle(p.z, p.w, t.z, t.w, sv.z, mr, kr, kd, m0r, sd0r);
        }
    }

    // remainder float4s (0 for this shape, kept for generality)
    if (blockIdx.x == 0 && tid < rem) {
        float4 p  = __ldg(&pred[rem_base + tid]);
        float4 t  = __ldg(&tru [rem_base + tid]);
        float4 sv = __ldg(&site[rem_base + tid]);
        acc += gd_angle(p.x, p.y, t.x, t.y, sv.x, mr, kr, kd, m0r, sd0r);
        acc += gd_angle(p.z, p.w, t.z, t.w, sv.z, mr, kr, kd, m0r, sd0r);
    }

    // intra-block reduce
    #pragma unroll
    for (int o = 16; o > 0; o >>= 1)
        acc += __shfl_xor_sync(0xffffffffu, acc, o);

    __shared__ float sm[NTHREADS / 32];
    __shared__ bool is_last;
    int lane = tid & 31;
    int warp = tid >> 5;
    if (lane == 0) sm[warp] = acc;
    __syncthreads();

    if (tid == 0) {
        float v = 0.0f;
        #pragma unroll
        for (int w = 0; w < NTHREADS / 32; w++) v += sm[w];
        g_partials[blockIdx.x] = v;
        __threadfence();
        unsigned int ticket = atomicAdd(&g_count, 1u);
        is_last = (ticket == gridDim.x - 1);
        if (is_last) g_count = 0;   // reset for next graph replay
    }
    __syncthreads();

    // last block: deterministic final reduction
    if (is_last) {
        float v = 0.0f;
        for (int j = tid; j < NBLOCKS; j += NTHREADS)
            v += g_partials[j];
        #pragma unroll
        for (int o = 16; o > 0; o >>= 1)
            v += __shfl_xor_sync(0xffffffffu, v, o);
        if (lane == 0) sm[warp] = v;
        __syncthreads();
        if (tid == 0) {
            float t = 0.0f;
            #pragma unroll
            for (int w = 0; w < NTHREADS / 32; w++) t += sm[w];
            out[0] = t * scale;
        }
    }
}

extern "C" void kernel_launch(void* const* d_in, const int* in_sizes, int n_in,
                              void* d_out, int out_size)
{
    const float4* pred = (const float4*)d_in[0];
    const float4* tru  = (const float4*)d_in[1];
    const float*  ms   = (const float*)d_in[2];
    const float*  ss   = (const float*)d_in[3];
    const float4* site = (const float4*)d_in[4];
    const float*  mn   = (const float*)d_in[5];
    const float*  sd   = (const float*)d_in[6];

    int n4 = in_sizes[0] / 4;                 // float4 count (2 rows each)
    int n_tiles = n4 / TILE_F4;               // 8192 for this shape
    int rem_base = n_tiles * TILE_F4;
    int rem = n4 - rem_base;                  // 0 here
    long long B = (long long)in_sizes[0] / 2; // row count
    float scale = (float)((double)EARTH_R / (double)B);

    gd_cpasync<<<NBLOCKS, NTHREADS>>>(pred, tru, site, ms, ss, mn, sd,
                                      n_tiles, rem_base, rem, scale,
                                      (float*)d_out);
}

// round 9
// speedup vs baseline: 1.0809x; 1.0604x over previous
#include <cuda_runtime.h>
#include <cstdint>

#define DEG2RAD  0.017453292519943295f
#define PI_F     3.14159265358979323846f
#define PIO2_F   1.57079632679489661923f
#define EARTH_R  6371.009f

#define NBLOCKS  1184    // 148 SMs * 8 CTAs
#define NTHREADS 256

__device__ float g_partials[NBLOCKS];
__device__ unsigned int g_count = 0;

__device__ __forceinline__ float sqrt_approx(float x)
{
    float r;
    asm("sqrt.approx.f32 %0, %1;" : "=f"(r) : "f"(x));
    return r;
}

// Streaming load: non-coherent, with 256B L2 promotion (halves DRAM request
// count for pure-streaming reads; promoted bytes are always consumed by the
// neighboring warp in the same wave).
__device__ __forceinline__ float4 ldg_stream(const float4* p)
{
    float4 v;
    asm("ld.global.nc.L2::256B.v4.f32 {%0,%1,%2,%3}, [%4];"
        : "=f"(v.x), "=f"(v.y), "=f"(v.z), "=f"(v.w) : "l"(p));
    return v;
}

// atan2(num, den) for num >= 0, result in [0, pi].
__device__ __forceinline__ float fast_atan2_pos(float num, float den)
{
    float ax = fabsf(den);
    float mn = fminf(num, ax);
    float mx = fmaxf(fmaxf(num, ax), 1e-30f);
    float z  = __fdividef(mn, mx);
    float z2 = z * z;
    float p = -0.0117212f;
    p = fmaf(p, z2,  0.05265332f);
    p = fmaf(p, z2, -0.11643287f);
    p = fmaf(p, z2,  0.19354346f);
    p = fmaf(p, z2, -0.33262347f);
    p = fmaf(p, z2,  0.99997726f);
    float a = z * p;
    if (num > ax)  a = PIO2_F - a;
    if (den < 0.f) a = PI_F - a;
    return a;
}

// sin/cos by Taylor poly, valid |x| <= 0.5 rad (err < 5e-9).
__device__ __forceinline__ void sincos_small(float x, float* s, float* c)
{
    float x2 = x * x;
    float ps = fmaf(x2, -1.9841270e-4f, 8.3333333e-3f);
    ps = fmaf(x2, ps, -0.16666667f);
    ps = fmaf(x2, ps, 1.0f);
    *s = x * ps;
    float pc = fmaf(x2, 2.4801587e-5f, -1.3888889e-3f);
    pc = fmaf(x2, pc, 4.1666667e-2f);
    pc = fmaf(x2, pc, -0.5f);
    pc = fmaf(x2, pc, 1.0f);
    *c = pc;
}

__device__ __forceinline__ float gd_angle(float p_lat, float p_lng,
                                          float t_lat, float t_lng,
                                          float s_lat,
                                          float mr, float kr, float kd,
                                          float m0r, float sd0r)
{
    float site_r = fmaf(s_lat, sd0r, m0r);
    float lat1 = fmaf(p_lat, kr, mr) + site_r;
    float lat2 = fmaf(t_lat, kr, mr) + site_r;
    lat1 = fminf(fmaxf(lat1, -PIO2_F), PIO2_F);  // clamp predicted lat only
    float delta = (t_lng - p_lng) * kd;

    float s1, c1, s2, c2, sd, cd;
    __sincosf(lat1, &s1, &c1);
    __sincosf(lat2, &s2, &c2);
    sincos_small(delta, &sd, &cd);

    float a = c2 * sd;
    float b = fmaf(c1, s2, -(s1 * c2) * cd);
    float num = sqrt_approx(fmaf(a, a, b * b));
    float den = fmaf(s1, s2, (c1 * c2) * cd);
    return fast_atan2_pos(num, den);
}

__global__ void __launch_bounds__(NTHREADS)
gd_fused(const float4* __restrict__ pred,
         const float4* __restrict__ tru,
         const float4* __restrict__ site,
         const float* __restrict__ mean_speed,
         const float* __restrict__ std_speed,
         const float* __restrict__ mean,
         const float* __restrict__ stdv,
         int n4, float scale, float* __restrict__ out)
{
    const float mr   = __ldg(&mean_speed[0]) * DEG2RAD;
    const float kr   = __ldg(&std_speed[0]) * DEG2RAD;
    const float kd   = __ldg(&std_speed[1]) * DEG2RAD;
    const float m0r  = __ldg(&mean[0]) * DEG2RAD;
    const float sd0r = __ldg(&stdv[0]) * DEG2RAD;

    float acc = 0.0f;
    const int idx = blockIdx.x * blockDim.x + threadIdx.x;
    const int stride = gridDim.x * blockDim.x;

    if (idx < n4) {
        float4 p = ldg_stream(&pred[idx]);
        float4 t = ldg_stream(&tru[idx]);
        float4 s = ldg_stream(&site[idx]);

        for (int i = idx; i < n4; i += stride) {
            int j = i + stride;
            int jc = (j < n4) ? j : i;      // safe (redundant) address on tail
            float4 pn = ldg_stream(&pred[jc]);
            float4 tn = ldg_stream(&tru[jc]);
            float4 sn = ldg_stream(&site[jc]);

            acc += gd_angle(p.x, p.y, t.x, t.y, s.x, mr, kr, kd, m0r, sd0r);
            acc += gd_angle(p.z, p.w, t.z, t.w, s.z, mr, kr, kd, m0r, sd0r);

            p = pn; t = tn; s = sn;
        }
    }

    // intra-block reduce
    #pragma unroll
    for (int o = 16; o > 0; o >>= 1)
        acc += __shfl_xor_sync(0xffffffffu, acc, o);

    __shared__ float sm[NTHREADS / 32];
    __shared__ bool is_last;
    int lane = threadIdx.x & 31;
    int warp = threadIdx.x >> 5;
    if (lane == 0) sm[warp] = acc;
    __syncthreads();

    if (threadIdx.x == 0) {
        float v = 0.0f;
        #pragma unroll
        for (int w = 0; w < NTHREADS / 32; w++) v += sm[w];
        g_partials[blockIdx.x] = v;
        __threadfence();
        unsigned int ticket = atomicAdd(&g_count, 1u);
        is_last = (ticket == gridDim.x - 1);
        if (is_last) g_count = 0;   // reset for next graph replay
    }
    __syncthreads();

    // last block: deterministic final reduction
    if (is_last) {
        float v = 0.0f;
        for (int j = threadIdx.x; j < NBLOCKS; j += NTHREADS)
            v += g_partials[j];
        #pragma unroll
        for (int o = 16; o > 0; o >>= 1)
            v += __shfl_xor_sync(0xffffffffu, v, o);
        if (lane == 0) sm[warp] = v;
        __syncthreads();
        if (threadIdx.x == 0) {
            float t = 0.0f;
            #pragma unroll
            for (int w = 0; w < NTHREADS / 32; w++) t += sm[w];
            out[0] = t * scale;
        }
    }
}

extern "C" void kernel_launch(void* const* d_in, const int* in_sizes, int n_in,
                              void* d_out, int out_size)
{
    const float4* pred = (const float4*)d_in[0];
    const float4* tru  = (const float4*)d_in[1];
    const float*  ms   = (const float*)d_in[2];
    const float*  ss   = (const float*)d_in[3];
    const float4* site = (const float4*)d_in[4];
    const float*  mn   = (const float*)d_in[5];
    const float*  sd   = (const float*)d_in[6];

    int n4 = in_sizes[0] / 4;                 // float4 count (2 rows each)
    long long B = (long long)in_sizes[0] / 2; // row count
    float scale = (float)((double)EARTH_R / (double)B);

    gd_fused<<<NBLOCKS, NTHREADS>>>(pred, tru, site, ms, ss, mn, sd,
                                    n4, scale, (float*)d_out);
}